// round 7
// baseline (speedup 1.0000x reference)
#include <cuda_runtime.h>
#include <cuda_fp16.h>

// SlinkyForcePredictor — fused per-edge kernel, v6.
// v5 showed the kernel is warp-supply-bound (issue fell 68->54% with no dur
// change; occ 24.9%). v6: 640 threads / 20 warps / TE=40 (+25% warp supply).
// Stage-3 loop de-unrolled + edge-sequential body to fit the 102-reg cap.

#define MULC 50
#define NBC 10
#define HIDC 100
#define TE 40
#define NTHREADS 640

typedef unsigned long long u64;

struct SM {
  float X[TE][MULC][12];      // phys: [x1,x2,x3,x0,x4,x5,x6,x7,x8,a0,a1,a2]
  float s[TE][MULC];
  float shv[TE][12];
  float emb[TE][12];
  __half Wsc[3][MULC][MULC];
  __half Wl1[MULC][MULC];
  __half Wl2[3][MULC][MULC];
  __half Wg[MULC][MULC];
  float W1[NBC][HIDC];
  float b1[104];
  __half W2[HIDC][152];       // [h][u*3+p]
};

#define HID(le,h) sm->X[le][(h) >> 1][9 + ((h) & 1)]

__device__ __forceinline__ float geluf(float x) {
  float x3 = x * x * x;
  float t = tanhf(0.7978845608028654f * (x + 0.044715f * x3));
  return 0.5f * x * (1.0f + t);
}
__device__ __forceinline__ float sigmoidf(float x) { return 1.0f / (1.0f + expf(-x)); }
__device__ __forceinline__ float siluf(float x) { return x * sigmoidf(x); }

__device__ __forceinline__ float2 ldh2(const __half* p) {
  return __half22float2(*reinterpret_cast<const __half2*>(p));
}
__device__ __forceinline__ u64 pk(float lo, float hi) {
  u64 r; asm("mov.b64 %0, {%1, %2};" : "=l"(r) : "f"(lo), "f"(hi)); return r;
}
__device__ __forceinline__ void upk(float& lo, float& hi, u64 v) {
  asm("mov.b64 {%0, %1}, %2;" : "=f"(lo), "=f"(hi) : "l"(v));
}
__device__ __forceinline__ void fma2(u64& d, u64 a, u64 b) {
  asm("fma.rn.f32x2 %0, %1, %2, %3;" : "=l"(d) : "l"(a), "l"(b), "l"(d));
}

__global__ __launch_bounds__(NTHREADS, 1)
void slinky_kernel(const float* __restrict__ node_pos,
                   const float* __restrict__ bar_alpha,
                   const float* __restrict__ W_embed,
                   const float* __restrict__ Wsc_g,
                   const float* __restrict__ Wlin1_g,
                   const float* __restrict__ W1_g,
                   const float* __restrict__ b1_g,
                   const float* __restrict__ W2_g,
                   const float* __restrict__ Wlin2_g,
                   const float* __restrict__ Wgate_g,
                   const float* __restrict__ Wout_g,
                   float* __restrict__ out)
{
  extern __shared__ __align__(16) float smem_raw[];
  SM* sm = reinterpret_cast<SM*>(smem_raw);

  const int tid = threadIdx.x;
  const int w   = tid >> 5;
  const int ln  = tid & 31;
  const int e0  = 2 * w;
  const int e1  = 2 * w + 1;
  const bool act = (ln < 25);
  const int u0 = 2 * ln;

  const float INVS50 = 0.1414213562373095f;
  const float CS = 0.9238795325112867f;
  const float CX = 0.3826834323650898f;
  const float CXK0 = CX * 0.05773502691896258f;
  const float CXK1 = CX * 0.02357022603955159f;
  const float CXK2 = CX * 0.01825741858350554f;

  // ---------------- preprocess ----------------
  {
    const int half = ln >> 4;
    const int l16 = ln & 15;
    const int le = e0 + half;
    const int eg = blockIdx.x * TE + le;
    const float* p6 = node_pos + (size_t)eg * 6;
    float ex = p6[1] - p6[0];
    float ey = p6[3] - p6[2];
    float ez = p6[5] - p6[4];
    float r = sqrtf(ex * ex + ey * ey + ez * ez);
    float inv = 1.0f / fmaxf(r, 1e-12f);
    float vx = ex * inv, vy = ey * inv, vz = ez * inv;
    if (l16 == 0) {
      const float s3 = 1.7320508075688772f;
      const float s5 = 2.23606797749979f;
      const float s15 = 3.872983346207417f;
      float* shp = sm->shv[le];
      shp[0] = 1.0f;
      shp[1] = s3 * vx;
      shp[2] = s3 * vy;
      shp[3] = s3 * vz;
      shp[4] = s15 * vx * vz;
      shp[5] = s15 * vx * vy;
      shp[6] = s5 * (vy * vy - 0.5f * (vx * vx + vz * vz));
      shp[7] = s15 * vy * vz;
      shp[8] = 0.5f * s15 * (vz * vz - vx * vx);
    }
    if (l16 < NBC) {
      const float step = 4.0f / 11.0f;
      float c = (float)(l16 + 1) * step;
      float diff = (r - c) / step;
      float up = diff + 1.0f, um = 1.0f - diff;
      float ua = (up > 0.0f) ? expf(-1.0f / up) : 0.0f;
      float ub = (um > 0.0f) ? expf(-1.0f / um) : 0.0f;
      sm->emb[le][l16] = (1.14136f * 7.3890560989306495f * 3.1622776601683795f) * ua * ub;
    }
  }
  if (act) {
    const int geb = blockIdx.x * TE;
    #pragma unroll
    for (int e = 0; e < 2; e++) {
      int le = e0 + e;
      int eg = geb + le;
      float ba_s = bar_alpha[2 * eg];
      float ba_d = bar_alpha[2 * eg + 1];
      #pragma unroll
      for (int ch = 0; ch < 2; ch++) {
        int u = u0 + ch;
        float we = W_embed[u];
        sm->s[le][u] = ba_s * we;
        float* xr = sm->X[le][u];
        xr[0] = 0.0f; xr[1] = 0.0f; xr[2] = 0.0f;
        xr[3] = ba_d * we;                        // x0 lives at phys 3
        xr[4] = 0.0f; xr[5] = 0.0f; xr[6] = 0.0f; xr[7] = 0.0f; xr[8] = 0.0f;
      }
    }
  }

  // ---------------- layers ----------------
  for (int i = 0; i < 3; i++) {
    __syncthreads();
    // weight staging: fp32 global -> fp16 smem
    {
      const float2* g2 = reinterpret_cast<const float2*>(Wsc_g + i * 7500);
      __half2* dh = reinterpret_cast<__half2*>(&sm->Wsc[0][0][0]);
      for (int t = tid; t < 3750; t += NTHREADS) dh[t] = __float22half2_rn(g2[t]);
      g2 = reinterpret_cast<const float2*>(Wlin1_g + i * 7500);
      dh = reinterpret_cast<__half2*>(&sm->Wl1[0][0]);
      for (int t = tid; t < 1250; t += NTHREADS) dh[t] = __float22half2_rn(g2[t]);
      g2 = reinterpret_cast<const float2*>(Wlin2_g + i * 7500);
      dh = reinterpret_cast<__half2*>(&sm->Wl2[0][0][0]);
      for (int t = tid; t < 3750; t += NTHREADS) dh[t] = __float22half2_rn(g2[t]);
      g2 = reinterpret_cast<const float2*>(Wgate_g + i * 2500);
      dh = reinterpret_cast<__half2*>(&sm->Wg[0][0]);
      for (int t = tid; t < 1250; t += NTHREADS) dh[t] = __float22half2_rn(g2[t]);
      const float4* g4 = reinterpret_cast<const float4*>(W1_g + i * 1000);
      float4* d4 = reinterpret_cast<float4*>(&sm->W1[0][0]);
      for (int t = tid; t < 250; t += NTHREADS) d4[t] = g4[t];
      if (tid < 100) sm->b1[tid] = b1_g[i * 100 + tid];
      const float* g = W2_g + i * 75000;
      for (int t = tid; t < 15000; t += NTHREADS) {
        int h = t / 150;
        int c = t - h * 150;
        int u = c / 3;
        int p = c - u * 3;
        sm->W2[h][c] = __float2half_rn(g[h * 750 + u * 15 + p]);
      }
    }
    __syncthreads();

    // ---- stage 1a: radial MLP hidden -> overlay slots 9/10 ----
    #pragma unroll
    for (int j = 0; j < 4; j++) {
      int h = ln + 32 * j;
      if (h < HIDC) {
        float a0 = 0.0f, a1 = 0.0f;
        #pragma unroll
        for (int b = 0; b < NBC; b++) {
          float w1 = sm->W1[b][h];
          a0 = fmaf(sm->emb[e0][b], w1, a0);
          a1 = fmaf(sm->emb[e1][b], w1, a1);
        }
        HID(e0, h) = geluf(a0 * 0.31622776601683794f + sm->b1[h]);
        HID(e1, h) = geluf(a1 * 0.31622776601683794f + sm->b1[h]);
      }
    }
    __syncwarp();

    // ---- stage 1b: wv (packed) ----
    u64 WV0[3] = {0ull, 0ull, 0ull};
    u64 WV1[3] = {0ull, 0ull, 0ull};
    if (act) {
      #pragma unroll 4
      for (int h = 0; h < HIDC; h++) {
        float h0v = HID(e0, h);
        float h1v = HID(e1, h);
        const __half* w2p = &sm->W2[h][6 * ln];
        float2 c0 = ldh2(w2p), c1 = ldh2(w2p + 2), c2 = ldh2(w2p + 4);
        u64 C0 = pk(c0.x, c0.y), C1 = pk(c1.x, c1.y), C2 = pk(c2.x, c2.y);
        u64 H0 = pk(h0v, h0v), H1 = pk(h1v, h1v);
        fma2(WV0[0], H0, C0); fma2(WV0[1], H0, C1); fma2(WV0[2], H0, C2);
        fma2(WV1[0], H1, C0); fma2(WV1[1], H1, C1); fma2(WV1[2], H1, C2);
      }
    }
    float wv[2][2][3];
    upk(wv[0][0][0], wv[0][0][1], WV0[0]);
    upk(wv[0][0][2], wv[0][1][0], WV0[1]);
    upk(wv[0][1][1], wv[0][1][2], WV0[2]);
    upk(wv[1][0][0], wv[1][0][1], WV1[0]);
    upk(wv[1][0][2], wv[1][1][0], WV1[1]);
    upk(wv[1][1][1], wv[1][1][2], WV1[2]);

    // ---- stage 2: source matvecs (packed over ch) ----
    u64 H0p = 0ull, H1p = 0ull, SC0p = 0ull, SC1p = 0ull;
    if (act) {
      #pragma unroll 5
      for (int t = 0; t < MULC; t++) {
        float s0 = sm->s[e0][t];
        float s1 = sm->s[e1][t];
        float2 wl = ldh2(&sm->Wl1[t][u0]);
        float2 ws = ldh2(&sm->Wsc[0][t][u0]);
        u64 WL = pk(wl.x, wl.y), WS = pk(ws.x, ws.y);
        u64 S0 = pk(s0, s0), S1 = pk(s1, s1);
        fma2(H0p, S0, WL);
        fma2(SC0p, S0, WS);
        fma2(H1p, S1, WL);
        fma2(SC1p, S1, WS);
      }
    }
    float h0a[2][2], sca[2][2];
    upk(h0a[0][0], h0a[0][1], H0p);
    upk(h0a[1][0], h0a[1][1], H1p);
    upk(sca[0][0], sca[0][1], SC0p);
    upk(sca[1][0], sca[1][1], SC1p);
    __syncwarp();
    if (act) {
      #pragma unroll
      for (int e = 0; e < 2; e++) {
        int le = e0 + e;
        #pragma unroll
        for (int ch = 0; ch < 2; ch++) {
          int u = u0 + ch;
          float h0 = h0a[e][ch] * INVS50;
          float* xr = sm->X[le][u];
          xr[9]  = h0 * wv[e][ch][0] * 0.1f;
          xr[10] = h0 * wv[e][ch][1] * 0.1f;
          xr[11] = h0 * wv[e][ch][2] * 0.1f;
          sm->s[le][u] = siluf(CS * sca[e][ch] * INVS50);
        }
      }
    }
    __syncwarp();

    // ---- stage 3: packed f32x2; pairs (x1,x2)(x3,x0)(x4,x5)(x6,x7)(x8,a0)(a1,a2) ----
    u64 A[2][2][6] = {};
    if (act) {
      #pragma unroll 1
      for (int u = 0; u < MULC; u++) {
        float2 ws0 = ldh2(&sm->Wsc[0][u][u0]);
        float2 ws1 = ldh2(&sm->Wsc[1][u][u0]);
        float2 ws2 = ldh2(&sm->Wsc[2][u][u0]);
        float2 l0 = ldh2(&sm->Wl2[0][u][u0]);
        float2 l1 = ldh2(&sm->Wl2[1][u][u0]);
        float2 l2 = ldh2(&sm->Wl2[2][u][u0]);
        u64 Q0x = pk(ws1.x, ws1.x);
        u64 Q1x = pk(ws1.x, ws0.x);
        u64 Q2x = pk(ws2.x, ws2.x);
        u64 Q3x = pk(ws2.x, l0.x);
        u64 Q4x = pk(l1.x, l2.x);
        u64 Q0y = pk(ws1.y, ws1.y);
        u64 Q1y = pk(ws1.y, ws0.y);
        u64 Q2y = pk(ws2.y, ws2.y);
        u64 Q3y = pk(ws2.y, l0.y);
        u64 Q4y = pk(l1.y, l2.y);
        {
          const ulonglong2* xp = reinterpret_cast<const ulonglong2*>(sm->X[e0][u]);
          ulonglong2 xa = xp[0], xb = xp[1], xc = xp[2];
          fma2(A[0][0][0], xa.x, Q0x);
          fma2(A[0][0][1], xa.y, Q1x);
          fma2(A[0][0][2], xb.x, Q2x);
          fma2(A[0][0][3], xb.y, Q2x);
          fma2(A[0][0][4], xc.x, Q3x);
          fma2(A[0][0][5], xc.y, Q4x);
          fma2(A[0][1][0], xa.x, Q0y);
          fma2(A[0][1][1], xa.y, Q1y);
          fma2(A[0][1][2], xb.x, Q2y);
          fma2(A[0][1][3], xb.y, Q2y);
          fma2(A[0][1][4], xc.x, Q3y);
          fma2(A[0][1][5], xc.y, Q4y);
        }
        {
          const ulonglong2* xp = reinterpret_cast<const ulonglong2*>(sm->X[e1][u]);
          ulonglong2 xa = xp[0], xb = xp[1], xc = xp[2];
          fma2(A[1][0][0], xa.x, Q0x);
          fma2(A[1][0][1], xa.y, Q1x);
          fma2(A[1][0][2], xb.x, Q2x);
          fma2(A[1][0][3], xb.y, Q2x);
          fma2(A[1][0][4], xc.x, Q3x);
          fma2(A[1][0][5], xc.y, Q4x);
          fma2(A[1][1][0], xa.x, Q0y);
          fma2(A[1][1][1], xa.y, Q1y);
          fma2(A[1][1][2], xb.x, Q2y);
          fma2(A[1][1][3], xb.y, Q2y);
          fma2(A[1][1][4], xc.x, Q3y);
          fma2(A[1][1][5], xc.y, Q4y);
        }
      }
    }
    __syncwarp();   // all lanes done reading X
    if (act) {
      #pragma unroll
      for (int e = 0; e < 2; e++) {
        int le = e0 + e;
        const float* shl = sm->shv[le];
        #pragma unroll
        for (int ch = 0; ch < 2; ch++) {
          int u = u0 + ch;
          float ac0, ac1, ac2, ac3, ac4, ac5, ac6, ac7, ac8, b0, b1v, b2;
          upk(ac1, ac2, A[e][ch][0]);
          upk(ac3, ac0, A[e][ch][1]);
          upk(ac4, ac5, A[e][ch][2]);
          upk(ac6, ac7, A[e][ch][3]);
          upk(ac8, b0,  A[e][ch][4]);
          upk(b1v, b2,  A[e][ch][5]);
          float* xr = sm->X[le][u];
          xr[3] = CS * INVS50 * ac0 + CXK0 * b0;
          xr[0] = CS * INVS50 * ac1 + CXK1 * b1v * shl[1];
          xr[1] = CS * INVS50 * ac2 + CXK1 * b1v * shl[2];
          xr[2] = CS * INVS50 * ac3 + CXK1 * b1v * shl[3];
          xr[4] = CS * INVS50 * ac4 + CXK2 * b2 * shl[4];
          xr[5] = CS * INVS50 * ac5 + CXK2 * b2 * shl[5];
          xr[6] = CS * INVS50 * ac6 + CXK2 * b2 * shl[6];
          xr[7] = CS * INVS50 * ac7 + CXK2 * b2 * shl[7];
          xr[8] = CS * INVS50 * ac8 + CXK2 * b2 * shl[8];
        }
      }
    }
    __syncwarp();

    // ---- stage 4: gate (packed over ch) ----
    u64 GA0 = 0ull, GA1 = 0ull;
    if (act) {
      #pragma unroll 5
      for (int u = 0; u < MULC; u++) {
        float t0 = sm->X[e0][u][3];   // x0 at phys 3
        float t1 = sm->X[e1][u][3];
        float2 wg = ldh2(&sm->Wg[u][u0]);
        u64 WG = pk(wg.x, wg.y);
        u64 T0 = pk(t0, t0), T1 = pk(t1, t1);
        fma2(GA0, T0, WG);
        fma2(GA1, T1, WG);
      }
    }
    float ga[2][2];
    upk(ga[0][0], ga[0][1], GA0);
    upk(ga[1][0], ga[1][1], GA1);
    __syncwarp();
    if (act) {
      #pragma unroll
      for (int e = 0; e < 2; e++) {
        int le = e0 + e;
        #pragma unroll
        for (int ch = 0; ch < 2; ch++) {
          int u = u0 + ch;
          float g = sigmoidf(ga[e][ch] * INVS50);
          float* xr = sm->X[le][u];
          float4 Af = *reinterpret_cast<const float4*>(xr);
          float4 Bf = *reinterpret_cast<const float4*>(xr + 4);
          float x8 = xr[8];
          float4 qa = make_float4(Af.x * g, Af.y * g, Af.z * g, siluf(Af.w));
          float4 qb = make_float4(Bf.x * g, Bf.y * g, Bf.z * g, Bf.w * g);
          *reinterpret_cast<float4*>(xr)     = qa;
          *reinterpret_cast<float4*>(xr + 4) = qb;
          xr[8] = x8 * g;
        }
      }
    }
    __syncwarp();
  }

  // ---------------- output: x1..x3 at phys 0..2 ----------------
  {
    float p[2][3] = {};
    if (act) {
      float wo0 = Wout_g[u0];
      float wo1 = Wout_g[u0 + 1];
      #pragma unroll
      for (int e = 0; e < 2; e++) {
        int le = e0 + e;
        const float* r0 = sm->X[le][u0];
        const float* r1 = sm->X[le][u0 + 1];
        p[e][0] = r0[0] * wo0 + r1[0] * wo1;
        p[e][1] = r0[1] * wo0 + r1[1] * wo1;
        p[e][2] = r0[2] * wo0 + r1[2] * wo1;
      }
    }
    #pragma unroll
    for (int off = 16; off; off >>= 1) {
      #pragma unroll
      for (int e = 0; e < 2; e++) {
        p[e][0] += __shfl_xor_sync(0xffffffffu, p[e][0], off);
        p[e][1] += __shfl_xor_sync(0xffffffffu, p[e][1], off);
        p[e][2] += __shfl_xor_sync(0xffffffffu, p[e][2], off);
      }
    }
    if (ln == 0) {
      int eg0 = blockIdx.x * TE + e0;
      float* od = out + (size_t)(2 * eg0) * 3;
      od[0] = 0.0f; od[1] = 0.0f; od[2] = 0.0f;
      od[3] = p[0][0] * INVS50;
      od[4] = p[0][1] * INVS50;
      od[5] = p[0][2] * INVS50;
      od[6] = 0.0f; od[7] = 0.0f; od[8] = 0.0f;
      od[9]  = p[1][0] * INVS50;
      od[10] = p[1][1] * INVS50;
      od[11] = p[1][2] * INVS50;
    }
  }
}

extern "C" void kernel_launch(void* const* d_in, const int* in_sizes, int n_in,
                              void* d_out, int out_size) {
  const float* node_pos = (const float*)d_in[0];
  const float* bar_alpha = (const float*)d_in[1];
  const float* W_embed  = (const float*)d_in[2];
  const float* Wsc      = (const float*)d_in[3];
  const float* Wlin1    = (const float*)d_in[4];
  const float* W1       = (const float*)d_in[5];
  const float* b1       = (const float*)d_in[6];
  const float* W2       = (const float*)d_in[7];
  const float* Wlin2    = (const float*)d_in[8];
  const float* Wgate    = (const float*)d_in[9];
  const float* W_out    = (const float*)d_in[10];
  float* out = (float*)d_out;

  int E = in_sizes[0] / 6;          // 40000, /40 = 1000 blocks
  size_t smem = sizeof(SM);
  cudaFuncSetAttribute(slinky_kernel, cudaFuncAttributeMaxDynamicSharedMemorySize, (int)smem);
  slinky_kernel<<<E / TE, NTHREADS, smem>>>(node_pos, bar_alpha, W_embed, Wsc, Wlin1,
                                            W1, b1, W2, Wlin2, Wgate, W_out, out);
}